// round 4
// baseline (speedup 1.0000x reference)
#include <cuda_runtime.h>
#include <cuda_bf16.h>

// NoiseFilter: per (b,f) pair (65536 total):
//   taps:  ir0[j] = (1/128)(a0 + 2*sum_{k=1}^{63} a_k cos(pi*k*j/64) + a64*(-1)^j)
//          h[j]   = ir0[j] * 0.5*(1+cos(pi*j/64)),  j = 0..63
//   s[t] = 2*u[t]-1
//   Linear causal convolution with the 256-long impulse whose support is
//   [0,64) = h[d] and [192,256) = h[256-n]:
//     out[tau] = sum_{d=0}^{63} h[d] * ( Z[256+tau-d] + Z[tau+d] )
//   where Z[0..255] = 0, Z[256+t] = s[t].  (Second term self-gates: nonzero
//   only when tau+d >= 256, which is exactly the delayed anticausal tail.)

#define PAIRS   4
#define THREADS 256
#define ZSTRIDE 528   // 512 logical + 16 swizzle slack

// bank swizzle: sigma(i) = i + (i>>5); stride-4 lane patterns -> conflict-free
#define ZS(i) ((i) + ((i) >> 5))

__global__ __launch_bounds__(THREADS)
void noisefilter_kernel(const float* __restrict__ amp,    // [65536, 65]
                        const float* __restrict__ noise,  // [65536, 256]
                        float*       __restrict__ out)    // [65536, 256]
{
    __shared__ float Z[PAIRS][ZSTRIDE];   // zero-padded, swizzled signal
    __shared__ float a_sh[PAIRS][66];     // 2*amp
    __shared__ float h_sh[PAIRS][64];     // taps

    const int tid = threadIdx.x;
    const int p   = tid >> 6;        // pair within block (0..3)
    const int q   = tid & 63;        // lane within pair  (0..63)
    const long long pairBase = (long long)blockIdx.x * PAIRS;

    // ---- phase A: zero Z, load amp (doubled) ----
    float* Zf = (float*)Z;
    #pragma unroll
    for (int i = tid; i < PAIRS * ZSTRIDE; i += THREADS)
        Zf[i] = 0.f;
    for (int i = tid; i < PAIRS * 65; i += THREADS) {
        int pp = i / 65;
        int k  = i - pp * 65;
        a_sh[pp][k] = 2.f * amp[(pairBase + pp) * 65 + k];
    }
    __syncthreads();

    // ---- phase B: store s = 2u-1 into Z[256+t], compute taps h[j] ----
    {
        const float4* n4 = (const float4*)noise;
        float4 v = n4[(long long)blockIdx.x * (PAIRS * 64) + tid];
        float* Zp = Z[p];
        const int t = q * 4;
        Zp[ZS(256 + t + 0)] = 2.f * v.x - 1.f;
        Zp[ZS(256 + t + 1)] = 2.f * v.y - 1.f;
        Zp[ZS(256 + t + 2)] = 2.f * v.z - 1.f;
        Zp[ZS(256 + t + 3)] = 2.f * v.w - 1.f;
    }
    {
        const int j = q;
        const float* a = a_sh[p];
        // a[] holds 2*amp -> 0.5 factors restore the k=0 / k=64 edge terms
        float acc = 0.5f * a[0] + ((j & 1) ? -0.5f : 0.5f) * a[64];
        int m = 0;
        #pragma unroll
        for (int k = 1; k < 64; k++) {
            m = (m + j) & 127;                                 // (k*j) mod 128
            float c = __cosf((float)m * 0.04908738521234052f); // cos(pi*m/64)
            acc = fmaf(a[k], c, acc);
        }
        float cphi = __cosf((float)j * 0.04908738521234052f);  // cos(pi*j/64)
        h_sh[p][j] = acc * (1.f + cphi) * (1.f / 256.f);       // * win / 128
    }
    __syncthreads();

    // ---- phase C: causal conv + delayed tail, 4 outputs/thread ----
    {
        const float* Zp = Z[p];
        const float* h  = h_sh[p];
        const int t0 = q * 4;

        // A window: Z[256+t0+i-d] (slides down); B window: Z[t0+i+d] (slides up)
        float A0 = Zp[ZS(256 + t0 + 0)], A1 = Zp[ZS(256 + t0 + 1)],
              A2 = Zp[ZS(256 + t0 + 2)], A3 = Zp[ZS(256 + t0 + 3)];
        float B0 = Zp[ZS(t0 + 0)], B1 = Zp[ZS(t0 + 1)],
              B2 = Zp[ZS(t0 + 2)], B3 = Zp[ZS(t0 + 3)];

        float o0 = 0.f, o1 = 0.f, o2 = 0.f, o3 = 0.f;

        #pragma unroll
        for (int d = 0; d < 64; d++) {
            const float hd = h[d];
            o0 = fmaf(hd, A0 + B0, o0);
            o1 = fmaf(hd, A1 + B1, o1);
            o2 = fmaf(hd, A2 + B2, o2);
            o3 = fmaf(hd, A3 + B3, o3);
            // shift for d+1 (indices stay in [192,511] and [0,319])
            A3 = A2; A2 = A1; A1 = A0; A0 = Zp[ZS(256 + t0 - d - 1)];
            B0 = B1; B1 = B2; B2 = B3; B3 = Zp[ZS(t0 + 4 + d)];
        }

        ((float4*)out)[(pairBase + p) * 64 + q] = make_float4(o0, o1, o2, o3);
    }
}

extern "C" void kernel_launch(void* const* d_in, const int* in_sizes, int n_in,
                              void* d_out, int out_size)
{
    const float* amp   = (const float*)d_in[0];   // filter_bank [16,4096,65]
    const float* noise = (const float*)d_in[1];   // noise_u     [16,4096,256]
    float* out = (float*)d_out;                   // [16, 4096*256, 1]

    const int total_pairs = in_sizes[0] / 65;     // 65536
    const int blocks = total_pairs / PAIRS;       // 16384
    noisefilter_kernel<<<blocks, THREADS>>>(amp, noise, out);
}

// round 5
// speedup vs baseline: 2.4874x; 2.4874x over previous
#include <cuda_runtime.h>
#include <cuda_bf16.h>

// NoiseFilter, exact closed form (validated R3, rel_err 3.4e-7):
//   taps: ir0[j] = (1/128)(a0 + 2*sum_{k=1..63} a_k cos(pi*k*j/64) + a64*(-1)^j)
//         h[j]   = ir0[j] * 0.5*(1+cos(pi*j/64)),  j = 0..63
//   s[t] = 2*u[t]-1,  Z[0..255]=0, Z[256+t]=s[t]
//   out[tau] = sum_{d=0}^{63} h[d] * ( Z[256+tau-d] + Z[tau+d] )
// Second (wrap-tail) term is nonzero only for tau >= 192+... -> only output
// groups t0 >= 192 (q >= 48). Warps are specialized accordingly.

#define PAIRS   4
#define THREADS 256
#define ZSTRIDE 520            // 512 + 8 pad (keeps 16B row alignment)

__global__ __launch_bounds__(THREADS)
void noisefilter_kernel(const float* __restrict__ amp,    // [65536, 65]
                        const float* __restrict__ noise,  // [65536, 256]
                        float*       __restrict__ out)    // [65536, 256]
{
    __shared__ __align__(16) float Z[PAIRS][ZSTRIDE];  // zero-padded signal
    __shared__ __align__(16) float h_sh[PAIRS][68];    // taps (68: bank stagger, 16B rows)
    __shared__ float a_sh[PAIRS][68];                  // 2*amp
    __shared__ float cost[128];                        // cos(pi*m/64)

    const int tid = threadIdx.x;

    // tid -> (p, q) so that q<48 (no wrap-tail) fills warps 0..5 and
    // q>=48 (wrap-tail active) fills warps 6..7. Bijection onto (p, 0..63).
    int p, q;
    if (tid < 192) { p = tid / 48;        q = tid % 48; }
    else           { int r = tid - 192;   p = r >> 4;   q = 48 + (r & 15); }

    const long long pairBase = (long long)blockIdx.x * PAIRS;

    // ---- issue global noise load early ----
    const float4* n4 = (const float4*)noise;
    float4 v = n4[(pairBase + p) * 64 + q];

    // ---- phase A: zero Z, build cos table, load amp (doubled) ----
    {
        float* Zf = (float*)Z;
        #pragma unroll
        for (int i = tid; i < PAIRS * ZSTRIDE; i += THREADS) Zf[i] = 0.f;
    }
    if (tid < 128)
        cost[tid] = __cosf((float)tid * 0.04908738521234052f);   // pi/64
    for (int i = tid; i < PAIRS * 65; i += THREADS) {
        int pp = i / 65, k = i - pp * 65;
        a_sh[pp][k] = 2.f * amp[(pairBase + pp) * 65 + k];
    }
    __syncthreads();

    // ---- phase B: deposit s = 2u-1 into Z[256+t], compute taps ----
    {
        float4 s4 = make_float4(2.f * v.x - 1.f, 2.f * v.y - 1.f,
                                2.f * v.z - 1.f, 2.f * v.w - 1.f);
        ((float4*)(Z[p]))[64 + q] = s4;                 // Z[256+4q .. +3]
    }
    {
        const int j = q;
        const float* a = a_sh[p];
        // a[] holds 2*amp -> 0.5 factors restore k=0 / k=64 edge terms
        float acc = 0.5f * a[0] + ((j & 1) ? -0.5f : 0.5f) * a[64];
        int m = 0;
        #pragma unroll
        for (int k = 1; k < 64; k++) {
            m = (m + j) & 127;                          // (k*j) mod 128
            acc = fmaf(a[k], cost[m], acc);
        }
        h_sh[p][j] = acc * (1.f + cost[j]) * (1.f / 256.f);
    }
    __syncthreads();

    // ---- phase C: convolution, 4 outputs/thread, LDS.128 windows ----
    {
        const float4* Z4 = (const float4*)(Z[p]);
        const float4* H4 = (const float4*)(h_sh[p]);
        const int base = 64 + q;      // float4 index of Z[256+t0], t0 = 4q

        float o0 = 0.f, o1 = 0.f, o2 = 0.f, o3 = 0.f;
        float4 W_hi = Z4[base];       // A window (causal side), slides down

        if (q < 48) {
            // no wrap tail: out_i += h[d] * Z[256+t0+i-d]
            #pragma unroll
            for (int dq = 0; dq < 16; dq++) {
                const float4 hv   = H4[dq];
                const float4 W_lo = Z4[base - dq - 1];
                // d = 4dq
                o0 = fmaf(hv.x, W_hi.x, o0); o1 = fmaf(hv.x, W_hi.y, o1);
                o2 = fmaf(hv.x, W_hi.z, o2); o3 = fmaf(hv.x, W_hi.w, o3);
                // d = 4dq+1
                o0 = fmaf(hv.y, W_lo.w, o0); o1 = fmaf(hv.y, W_hi.x, o1);
                o2 = fmaf(hv.y, W_hi.y, o2); o3 = fmaf(hv.y, W_hi.z, o3);
                // d = 4dq+2
                o0 = fmaf(hv.z, W_lo.z, o0); o1 = fmaf(hv.z, W_lo.w, o1);
                o2 = fmaf(hv.z, W_hi.x, o2); o3 = fmaf(hv.z, W_hi.y, o3);
                // d = 4dq+3
                o0 = fmaf(hv.w, W_lo.y, o0); o1 = fmaf(hv.w, W_lo.z, o1);
                o2 = fmaf(hv.w, W_lo.w, o2); o3 = fmaf(hv.w, W_hi.x, o3);
                W_hi = W_lo;
            }
        } else {
            // wrap tail active: out_i += h[d]*(Z[256+t0+i-d] + Z[t0+i+d])
            float4 V_lo = Z4[q];      // B window (tail side), slides up
            #pragma unroll
            for (int dq = 0; dq < 16; dq++) {
                const float4 hv   = H4[dq];
                const float4 W_lo = Z4[base - dq - 1];
                const float4 V_hi = Z4[q + dq + 1];
                // d = 4dq
                o0 = fmaf(hv.x, W_hi.x + V_lo.x, o0);
                o1 = fmaf(hv.x, W_hi.y + V_lo.y, o1);
                o2 = fmaf(hv.x, W_hi.z + V_lo.z, o2);
                o3 = fmaf(hv.x, W_hi.w + V_lo.w, o3);
                // d = 4dq+1
                o0 = fmaf(hv.y, W_lo.w + V_lo.y, o0);
                o1 = fmaf(hv.y, W_hi.x + V_lo.z, o1);
                o2 = fmaf(hv.y, W_hi.y + V_lo.w, o2);
                o3 = fmaf(hv.y, W_hi.z + V_hi.x, o3);
                // d = 4dq+2
                o0 = fmaf(hv.z, W_lo.z + V_lo.z, o0);
                o1 = fmaf(hv.z, W_lo.w + V_lo.w, o1);
                o2 = fmaf(hv.z, W_hi.x + V_hi.x, o2);
                o3 = fmaf(hv.z, W_hi.y + V_hi.y, o3);
                // d = 4dq+3
                o0 = fmaf(hv.w, W_lo.y + V_lo.w, o0);
                o1 = fmaf(hv.w, W_lo.z + V_hi.x, o1);
                o2 = fmaf(hv.w, W_lo.w + V_hi.y, o2);
                o3 = fmaf(hv.w, W_hi.x + V_hi.z, o3);
                W_hi = W_lo;
                V_lo = V_hi;
            }
        }

        ((float4*)out)[(pairBase + p) * 64 + q] = make_float4(o0, o1, o2, o3);
    }
}

extern "C" void kernel_launch(void* const* d_in, const int* in_sizes, int n_in,
                              void* d_out, int out_size)
{
    const float* amp   = (const float*)d_in[0];   // filter_bank [16,4096,65]
    const float* noise = (const float*)d_in[1];   // noise_u     [16,4096,256]
    float* out = (float*)d_out;                   // [16, 4096*256, 1]

    const int total_pairs = in_sizes[0] / 65;     // 65536
    const int blocks = total_pairs / PAIRS;       // 16384
    noisefilter_kernel<<<blocks, THREADS>>>(amp, noise, out);
}

// round 6
// speedup vs baseline: 2.6513x; 1.0659x over previous
#include <cuda_runtime.h>
#include <cuda_bf16.h>
#include <cstdint>

// NoiseFilter, exact closed form (validated R3/R4, rel_err 3.4e-7):
//   taps: ir0[j] = (1/128)(a0 + 2*sum_{k=1..63} a_k cos(pi*k*j/64) + a64*(-1)^j)
//         h[j]   = ir0[j] * 0.5*(1+cos(pi*j/64)),  j = 0..63
//   s[t] = 2*u[t]-1,  Z[0..255]=0, Z[256+t]=s[t]
//   out[tau] = sum_{d=0}^{63} h[d] * ( Z[256+tau-d] + Z[tau+d] )
// Wrap-tail term (second) is nonzero only for output groups t0 >= 192 (q>=48);
// warps are specialized so warps 0-5 run the tail-free loop.

#define PAIRS   4
#define THREADS 256
#define ZSTRIDE 520            // 512 + 8 pad (keeps 16B row alignment)
#define PI64    0.04908738521234052f   // pi/64

// ---- f32x2 packed-math helpers (FFMA2 is only reachable via PTX) ----
#define PACK2(dst, lo, hi) \
    asm("mov.b64 %0, {%1, %2};" : "=l"(dst) \
        : "r"(__float_as_uint(lo)), "r"(__float_as_uint(hi)))
#define FMA2(acc, a, b) \
    asm("fma.rn.f32x2 %0, %1, %2, %0;" : "+l"(acc) : "l"(a), "l"(b))
#define ADD2(dst, a, b) \
    asm("add.rn.f32x2 %0, %1, %2;" : "=l"(dst) : "l"(a), "l"(b))
#define UNPACK2(lo, hi, v) \
    asm("mov.b64 {%0, %1}, %2;" : "=r"(lo), "=r"(hi) : "l"(v))

__global__ __launch_bounds__(THREADS)
void noisefilter_kernel(const float* __restrict__ amp,    // [65536, 65]
                        const float* __restrict__ noise,  // [65536, 256]
                        float*       __restrict__ out)    // [65536, 256]
{
    __shared__ __align__(16) float Z[PAIRS][ZSTRIDE];  // zero-padded signal
    __shared__ __align__(16) float h_sh[PAIRS][68];    // taps (68: 16B rows, bank stagger)
    __shared__ float a_sh[PAIRS][68];                  // 2*amp

    const int tid = threadIdx.x;

    // tid -> (p, q): q<48 (no wrap tail) fills warps 0..5; q>=48 warps 6..7.
    int p, q;
    if (tid < 192) { p = tid / 48;      q = tid % 48; }
    else           { int r = tid - 192; p = r >> 4;   q = 48 + (r & 15); }

    const long long pairBase = (long long)blockIdx.x * PAIRS;

    // ---- issue global noise load early ----
    const float4* n4 = (const float4*)noise;
    float4 v = n4[(pairBase + p) * 64 + q];

    // ---- phase A: zero Z (vectorized), load amp (doubled) ----
    {
        float4* Zf4 = (float4*)Z;
        #pragma unroll
        for (int i = tid; i < PAIRS * (ZSTRIDE / 4); i += THREADS)
            Zf4[i] = make_float4(0.f, 0.f, 0.f, 0.f);
    }
    for (int i = tid; i < PAIRS * 65; i += THREADS) {
        int pp = i / 65, k = i - pp * 65;
        a_sh[pp][k] = 2.f * amp[(pairBase + pp) * 65 + k];
    }
    __syncthreads();

    // ---- phase B: deposit s = 2u-1, compute taps (MUFU cos, no LDS gather) ----
    {
        float4 s4 = make_float4(2.f * v.x - 1.f, 2.f * v.y - 1.f,
                                2.f * v.z - 1.f, 2.f * v.w - 1.f);
        ((float4*)(Z[p]))[64 + q] = s4;                 // Z[256+4q .. +3]
    }
    {
        const int j = q;
        const float* a = a_sh[p];
        // a[] holds 2*amp -> 0.5 factors restore k=0 / k=64 edge terms
        float acc = 0.5f * a[0] + ((j & 1) ? -0.5f : 0.5f) * a[64];
        int m = 0;
        #pragma unroll
        for (int k = 1; k < 64; k++) {
            m = (m + j) & 127;                          // (k*j) mod 128
            acc = fmaf(a[k], __cosf((float)m * PI64), acc);
        }
        float cphi = __cosf((float)j * PI64);           // cos(pi*j/64)
        h_sh[p][j] = acc * (1.f + cphi) * (1.f / 256.f);
    }
    __syncthreads();

    // ---- phase C: convolution, 4 outputs/thread, packed FFMA2 ----
    {
        const float4* Z4 = (const float4*)(Z[p]);
        const float4* H4 = (const float4*)(h_sh[p]);
        const int base = 64 + q;       // float4 index of Z[256+t0], t0 = 4q

        uint64_t o01 = 0ull, o23 = 0ull;   // packed (o0,o1), (o2,o3)
        float4 B = Z4[base];               // causal window hi: Z[256+t0 .. +3]

        if (q < 48) {
            #pragma unroll
            for (int dq = 0; dq < 16; dq++) {
                const float4 hv = H4[dq];
                const float4 A  = Z4[base - dq - 1];   // Z[256+t0-4dq-4 .. -1]
                uint64_t Pb01, Pb23, Pa23, Pa12, Pa3b0, Pb12;
                PACK2(Pb01, B.x, B.y);  PACK2(Pb23, B.z, B.w);
                PACK2(Pa23, A.z, A.w);  PACK2(Pa12, A.y, A.z);
                PACK2(Pa3b0, A.w, B.x); PACK2(Pb12, B.y, B.z);
                uint64_t h0d, h1d, h2d, h3d;
                PACK2(h0d, hv.x, hv.x); PACK2(h1d, hv.y, hv.y);
                PACK2(h2d, hv.z, hv.z); PACK2(h3d, hv.w, hv.w);
                FMA2(o01, h0d, Pb01);  FMA2(o23, h0d, Pb23);   // d=4dq
                FMA2(o01, h1d, Pa3b0); FMA2(o23, h1d, Pb12);   // d=4dq+1
                FMA2(o01, h2d, Pa23);  FMA2(o23, h2d, Pb01);   // d=4dq+2
                FMA2(o01, h3d, Pa12);  FMA2(o23, h3d, Pa3b0);  // d=4dq+3
                B = A;
            }
        } else {
            float4 C = Z4[q];              // tail window lo: Z[t0 .. t0+3]
            #pragma unroll
            for (int dq = 0; dq < 16; dq++) {
                const float4 hv = H4[dq];
                const float4 A  = Z4[base - dq - 1];
                const float4 D  = Z4[q + dq + 1];      // Z[t0+4dq+4 .. +7]
                uint64_t Pb01, Pb23, Pa23, Pa12, Pa3b0, Pb12;
                PACK2(Pb01, B.x, B.y);  PACK2(Pb23, B.z, B.w);
                PACK2(Pa23, A.z, A.w);  PACK2(Pa12, A.y, A.z);
                PACK2(Pa3b0, A.w, B.x); PACK2(Pb12, B.y, B.z);
                uint64_t Pc01, Pc23, Pc12, Pc3d0, Pd01, Pd12;
                PACK2(Pc01, C.x, C.y);  PACK2(Pc23, C.z, C.w);
                PACK2(Pc12, C.y, C.z);  PACK2(Pc3d0, C.w, D.x);
                PACK2(Pd01, D.x, D.y);  PACK2(Pd12, D.y, D.z);
                uint64_t h0d, h1d, h2d, h3d;
                PACK2(h0d, hv.x, hv.x); PACK2(h1d, hv.y, hv.y);
                PACK2(h2d, hv.z, hv.z); PACK2(h3d, hv.w, hv.w);
                uint64_t S0, S1;
                ADD2(S0, Pb01, Pc01);  ADD2(S1, Pb23, Pc23);   // d=4dq
                FMA2(o01, h0d, S0);    FMA2(o23, h0d, S1);
                ADD2(S0, Pa3b0, Pc12); ADD2(S1, Pb12, Pc3d0);  // d=4dq+1
                FMA2(o01, h1d, S0);    FMA2(o23, h1d, S1);
                ADD2(S0, Pa23, Pc23);  ADD2(S1, Pb01, Pd01);   // d=4dq+2
                FMA2(o01, h2d, S0);    FMA2(o23, h2d, S1);
                ADD2(S0, Pa12, Pc3d0); ADD2(S1, Pa3b0, Pd12);  // d=4dq+3
                FMA2(o01, h3d, S0);    FMA2(o23, h3d, S1);
                B = A;
                C = D;
            }
        }

        uint32_t u0, u1, u2, u3;
        UNPACK2(u0, u1, o01);
        UNPACK2(u2, u3, o23);
        ((float4*)out)[(pairBase + p) * 64 + q] =
            make_float4(__uint_as_float(u0), __uint_as_float(u1),
                        __uint_as_float(u2), __uint_as_float(u3));
    }
}

extern "C" void kernel_launch(void* const* d_in, const int* in_sizes, int n_in,
                              void* d_out, int out_size)
{
    const float* amp   = (const float*)d_in[0];   // filter_bank [16,4096,65]
    const float* noise = (const float*)d_in[1];   // noise_u     [16,4096,256]
    float* out = (float*)d_out;                   // [16, 4096*256, 1]

    const int total_pairs = in_sizes[0] / 65;     // 65536
    const int blocks = total_pairs / PAIRS;       // 16384
    noisefilter_kernel<<<blocks, THREADS>>>(amp, noise, out);
}